// round 11
// baseline (speedup 1.0000x reference)
#include <cuda_runtime.h>
#include <cuda_fp16.h>
#include <cstdint>

// Problem dims
#define N_SAMPLES 2048
#define D_FEAT    64
#define P_PAIRS   2016
#define INNER     32
#define KDIM      64512   // P_PAIRS * INNER
#define HIDDEN    2048
#define CLASSES   10

// GEMM tiling
#define BM 128
#define BN 256
#define BK 64
#define STG 4
#define CHUNKS (KDIM / BK)                 // 1008
#define A_STAGE (BM * 128)                 // 16384 B (written in-kernel via STS)
#define B_STAGE (BN * 128)                 // 32768 B (bulk-TMA)
#define STAGE_B (A_STAGE + B_STAGE)        // 49152 B
#define OFF_MBAR (STG * STAGE_B)           // 196608
#define SMEM_GEMM (OFF_MBAR + 64)

// -------------------- scratch (device globals; no allocation) --------------------
__device__ __half g_bt[(size_t)HIDDEN * KDIM];      // Wv^T fp16, tiled [nb][c][row][kc^sw]
__device__ float  g_v [(size_t)N_SAMPLES * HIDDEN];
__device__ float  g_xT[(size_t)D_FEAT * N_SAMPLES];

// -------------------- helpers --------------------
__device__ __forceinline__ uint32_t smem_u32(const void* p) {
    return (uint32_t)__cvta_generic_to_shared(p);
}
__device__ __forceinline__ void mbar_init(uint32_t addr, uint32_t count) {
    asm volatile("mbarrier.init.shared.b64 [%0], %1;" :: "r"(addr), "r"(count) : "memory");
}
__device__ __forceinline__ void mbar_expect_tx(uint32_t addr, uint32_t bytes) {
    asm volatile("mbarrier.arrive.expect_tx.shared.b64 _, [%0], %1;"
                 :: "r"(addr), "r"(bytes) : "memory");
}
__device__ __forceinline__ void mbar_arrive(uint32_t addr) {
    asm volatile("mbarrier.arrive.shared.b64 _, [%0];" :: "r"(addr) : "memory");
}
__device__ __forceinline__ void mbar_wait(uint32_t addr, uint32_t parity) {
    uint32_t done;
    asm volatile(
        "{\n\t.reg .pred p;\n\t"
        "mbarrier.try_wait.parity.acquire.cta.shared::cta.b64 p, [%1], %2;\n\t"
        "selp.b32 %0, 1, 0, p;\n\t}"
        : "=r"(done) : "r"(addr), "r"(parity) : "memory");
    if (!done) {
        asm volatile(
            "{\n\t.reg .pred P1;\n\t"
            "W_%=:\n\t"
            "mbarrier.try_wait.parity.acquire.cta.shared::cta.b64 P1, [%0], %1, 0x989680;\n\t"
            "@P1 bra.uni D_%=;\n\t"
            "bra.uni W_%=;\n\t"
            "D_%=:\n\t}"
            :: "r"(addr), "r"(parity) : "memory");
    }
}
__device__ __forceinline__ void bulk_g2s(uint32_t dstSmem, const void* srcGmem,
                                         uint32_t bytes, uint32_t mbar) {
    asm volatile(
        "cp.async.bulk.shared::cluster.global.mbarrier::complete_tx::bytes [%0], [%1], %2, [%3];"
        :: "r"(dstSmem), "l"(srcGmem), "r"(bytes), "r"(mbar) : "memory");
}
__device__ __forceinline__ void ldsm_x4(uint32_t* r, uint32_t addr) {
    asm volatile("ldmatrix.sync.aligned.m8n8.x4.shared.b16 {%0,%1,%2,%3}, [%4];"
                 : "=r"(r[0]), "=r"(r[1]), "=r"(r[2]), "=r"(r[3]) : "r"(addr));
}
__device__ __forceinline__ void mma16816(float* c, const uint32_t* a, const uint32_t* b) {
    asm volatile(
        "mma.sync.aligned.m16n8k16.row.col.f32.f16.f16.f32 "
        "{%0,%1,%2,%3}, {%4,%5,%6,%7}, {%8,%9}, {%0,%1,%2,%3};"
        : "+f"(c[0]), "+f"(c[1]), "+f"(c[2]), "+f"(c[3])
        : "r"(a[0]), "r"(a[1]), "r"(a[2]), "r"(a[3]), "r"(b[0]), "r"(b[1]));
}
__device__ __forceinline__ uint32_t sw_off(int row, int kc) {
    return (uint32_t)(row * 128 + ((kc ^ (row & 7)) << 4));
}

// In-GEMM A-share compute: warp `wid` produces local rows wid*8..wid*8+7 of the
// A slab for chunk kp, writing swizzled fp16 into dstBase (smem). Lane layout:
// r4 = lane>>2 (row), i4 = lane&3 (16-k slice => pair (i4>>1), inner (i4&1)*16).
__device__ __forceinline__ void compute_A_share(
    const float* __restrict__ Wu, const float* __restrict__ bu,
    int kp, uint32_t dstBase, int lane, int wid, int mb)
{
    int r4 = lane >> 2, i4 = lane & 3;
    int rowLocal = wid * 8 + r4;
    int nGlob = mb * BM + rowLocal;
    int p = kp * 2 + (i4 >> 1);
    int ib = (i4 & 1) * 16;
    // closed-form inverse of triu_indices(64, k=1)
    int q = (P_PAIRS - 1) - p;
    int r = (int)((sqrtf((float)(8 * q + 1)) - 1.0f) * 0.5f);
    while ((r + 1) * (r + 2) / 2 <= q) r++;
    while (r * (r + 1) / 2 > q) r--;
    int a = 62 - r;
    int b = 63 - (q - r * (r + 1) / 2);
    float va = g_xT[(size_t)a * N_SAMPLES + nGlob];
    float vb = g_xT[(size_t)b * N_SAMPLES + nGlob];
    const float4* w0p = reinterpret_cast<const float4*>(Wu + (size_t)p * 64 + ib);
    const float4* w1p = reinterpret_cast<const float4*>(Wu + (size_t)p * 64 + 32 + ib);
    const float4* bp  = reinterpret_cast<const float4*>(bu + (size_t)p * 32 + ib);
    #pragma unroll
    for (int h = 0; h < 2; h++) {      // two 8-k halves -> two 16B units
        float4 wa0 = w0p[h * 2], wa1 = w0p[h * 2 + 1];
        float4 wb0 = w1p[h * 2], wb1 = w1p[h * 2 + 1];
        float4 b0  = bp[h * 2],  b1  = bp[h * 2 + 1];
        uint32_t hh[4];
        __half2 t;
        t = __floats2half2_rn(fmaxf(fmaf(va, wa0.x, fmaf(vb, wb0.x, b0.x)), 0.f),
                              fmaxf(fmaf(va, wa0.y, fmaf(vb, wb0.y, b0.y)), 0.f));
        hh[0] = *reinterpret_cast<uint32_t*>(&t);
        t = __floats2half2_rn(fmaxf(fmaf(va, wa0.z, fmaf(vb, wb0.z, b0.z)), 0.f),
                              fmaxf(fmaf(va, wa0.w, fmaf(vb, wb0.w, b0.w)), 0.f));
        hh[1] = *reinterpret_cast<uint32_t*>(&t);
        t = __floats2half2_rn(fmaxf(fmaf(va, wa1.x, fmaf(vb, wb1.x, b1.x)), 0.f),
                              fmaxf(fmaf(va, wa1.y, fmaf(vb, wb1.y, b1.y)), 0.f));
        hh[2] = *reinterpret_cast<uint32_t*>(&t);
        t = __floats2half2_rn(fmaxf(fmaf(va, wa1.z, fmaf(vb, wb1.z, b1.z)), 0.f),
                              fmaxf(fmaf(va, wa1.w, fmaf(vb, wb1.w, b1.w)), 0.f));
        hh[3] = *reinterpret_cast<uint32_t*>(&t);
        int kc = i4 * 2 + h;
        uint32_t addr = dstBase + sw_off(rowLocal, kc);
        asm volatile("st.shared.v4.b32 [%0], {%1,%2,%3,%4};"
                     :: "r"(addr), "r"(hh[0]), "r"(hh[1]), "r"(hh[2]), "r"(hh[3]) : "memory");
    }
}

// ==================== kernel 1: transpose x ====================
__global__ void k_transpose_x(const float* __restrict__ x) {
    int idx = blockIdx.x * blockDim.x + threadIdx.x;
    if (idx < N_SAMPLES * D_FEAT) {
        int n = idx >> 6, d = idx & 63;
        g_xT[(size_t)d * N_SAMPLES + n] = x[idx];
    }
}

// ==================== kernel 2: Wv fp32 -> g_bt fp16 (tiled, swizzled) ====================
#define CONV_BLOCKS ((HIDDEN / 64) * (KDIM / 32))   // 32 * 2016

__global__ void k_prep(const float* __restrict__ Wv) {
    int tid = threadIdx.x;
    int bid = blockIdx.x;
    int nBlocks = HIDDEN / 64;            // 32
    int nt0 = (bid % nBlocks) * 64;
    int kt0 = (bid / nBlocks) * 32;
    __shared__ float tile[32][65];
    #pragma unroll
    for (int pass = 0; pass < 8; pass++) {
        int idx = tid + pass * 256;
        int kl = idx >> 6, nl = idx & 63;
        tile[kl][nl] = Wv[(size_t)(kt0 + kl) * HIDDEN + nt0 + nl];
    }
    __syncthreads();
    int nl = tid >> 2, uq = tid & 3;
    __half hp[8];
    #pragma unroll
    for (int j = 0; j < 8; j++) hp[j] = __float2half(tile[uq * 8 + j][nl]);
    int n = nt0 + nl;
    int nb = n >> 8, rowB = n & 255;
    int c = kt0 >> 6;
    int kcq = ((kt0 & 63) >> 3) + uq;
    size_t unit = ((size_t)(nb * CHUNKS + c) * 256 + rowB) * 8 + (kcq ^ (rowB & 7));
    reinterpret_cast<uint4*>(g_bt)[unit] = *reinterpret_cast<uint4*>(hp);
}

// ==================== kernel 3: big GEMM v = relu(u @ Wv + bv) ====================
// R6 structure; A operand computed on-the-fly by consumer warps (8 rows each)
// into smem, B via bulk-TMA (warp0/lane0). mfull: 16 A-arrives + expect_tx arrive
// + B-bytes tx. No g_u round-trip.
__global__ void __launch_bounds__(512, 1) k_gemm(const float* __restrict__ Wu,
                                                 const float* __restrict__ bu,
                                                 const float* __restrict__ bv) {
    extern __shared__ char smem[];
    uint32_t sbase = smem_u32(smem);
    int tid = threadIdx.x;
    int lane = tid & 31;
    int wid = tid >> 5;          // 0..15
    int wm = wid >> 3;           // 0..1
    int wn = wid & 7;            // 0..7
    int nb = blockIdx.x;         // 8 n-blocks
    int mb = blockIdx.y;         // 16 m-blocks

    const char* gB = (const char*)g_bt + (size_t)nb * CHUNKS * B_STAGE;

    uint32_t mfull = sbase + OFF_MBAR;
    uint32_t mempty = sbase + OFF_MBAR + 32;
    if (tid == 0) {
        #pragma unroll
        for (int s = 0; s < STG; s++) {
            mbar_init(mfull + s * 8, 17);   // 16 A-share arrives + expect_tx arrive
            mbar_init(mempty + s * 8, 16);  // one per consumer warp
        }
    }
    __syncthreads();

    // prologue: producer B bulks for slots 0..2; all warps write A shares 0..2
    if (tid == 0) {
        #pragma unroll
        for (int s = 0; s < STG - 1; s++) {
            mbar_expect_tx(mfull + s * 8, B_STAGE);
            bulk_g2s(sbase + s * STAGE_B + A_STAGE, gB + (size_t)s * B_STAGE, B_STAGE, mfull + s * 8);
        }
    }
    #pragma unroll
    for (int s = 0; s < STG - 1; s++) {
        compute_A_share(Wu, bu, s, sbase + s * STAGE_B, lane, wid, mb);
        __syncwarp();
        if (lane == 0) mbar_arrive(mfull + s * 8);
    }

    int g = lane >> 3, sub = lane & 7;
    int rowA_base = wm * 64 + ((g & 1) << 3) + sub;
    int kcA_base  = g >> 1;
    int rowB_base = wn * 32 + ((g >> 1) << 3) + sub;
    int kcB_base  = g & 1;

    float acc[4][4][4];
    #pragma unroll
    for (int i = 0; i < 4; i++)
        #pragma unroll
        for (int j = 0; j < 4; j++)
            #pragma unroll
            for (int t = 0; t < 4; t++) acc[i][j][t] = 0.f;

    for (int k = 0; k < CHUNKS; k++) {
        int slot = k & 3;
        int kp = k + STG - 1;
        int sp = kp & 3;

        // producer: B bulk for stage kp (warp0 lane0)
        if (wid == 0 && lane == 0 && kp < CHUNKS) {
            if (kp >= STG) mbar_wait(mempty + sp * 8, ((kp >> 2) + 1) & 1);
            mbar_expect_tx(mfull + sp * 8, B_STAGE);
            bulk_g2s(sbase + sp * STAGE_B + A_STAGE, gB + (size_t)kp * B_STAGE, B_STAGE, mfull + sp * 8);
        }

        mbar_wait(mfull + slot * 8, (k >> 2) & 1);

        uint32_t aS = sbase + slot * STAGE_B;
        uint32_t bS = aS + A_STAGE;
        #pragma unroll
        for (int ks = 0; ks < 4; ks++) {
            uint32_t afr[4][4], bfr[2][4];
            #pragma unroll
            for (int q = 0; q < 2; q++) {
                int row = rowB_base + q * 16;
                ldsm_x4(bfr[q], bS + sw_off(row, ks * 2 + kcB_base));
            }
            #pragma unroll
            for (int mt = 0; mt < 4; mt++) {
                int row = rowA_base + mt * 16;
                ldsm_x4(afr[mt], aS + sw_off(row, ks * 2 + kcA_base));
            }
            #pragma unroll
            for (int mt = 0; mt < 4; mt++)
                #pragma unroll
                for (int nt = 0; nt < 4; nt++)
                    mma16816(acc[mt][nt], afr[mt], &bfr[nt >> 1][(nt & 1) * 2]);
        }
        if (lane == 0) mbar_arrive(mempty + slot * 8);

        // A-share for stage kp (all consumer warps), gated on stage sp drained
        if (kp < CHUNKS) {
            if (kp >= STG) mbar_wait(mempty + sp * 8, ((kp >> 2) + 1) & 1);
            compute_A_share(Wu, bu, kp, sbase + sp * STAGE_B, lane, wid, mb);
            __syncwarp();
            if (lane == 0) mbar_arrive(mfull + sp * 8);
        }
    }

    // epilogue: bias + relu, write fp32 v
    int rlo = lane >> 2;
    int cpair = (lane & 3) * 2;
    int bn0 = nb * BN, bm0 = mb * BM;
    #pragma unroll
    for (int mt = 0; mt < 4; mt++) {
        #pragma unroll
        for (int nt = 0; nt < 4; nt++) {
            int col = bn0 + wn * 32 + nt * 8 + cpair;
            float b0 = __ldg(bv + col), b1 = __ldg(bv + col + 1);
            int row0 = bm0 + wm * 64 + mt * 16 + rlo;
            float2 o0, o1;
            o0.x = fmaxf(acc[mt][nt][0] + b0, 0.f);
            o0.y = fmaxf(acc[mt][nt][1] + b1, 0.f);
            o1.x = fmaxf(acc[mt][nt][2] + b0, 0.f);
            o1.y = fmaxf(acc[mt][nt][3] + b1, 0.f);
            *reinterpret_cast<float2*>(g_v + (size_t)row0 * HIDDEN + col) = o0;
            *reinterpret_cast<float2*>(g_v + (size_t)(row0 + 8) * HIDDEN + col) = o1;
        }
    }
}

// ==================== kernel 4: head  out = v @ Wo + bo ====================
__global__ void k_final(const float* __restrict__ Wo, const float* __restrict__ bo,
                        float* __restrict__ out) {
    int n = blockIdx.x, tid = threadIdx.x;
    float acc[CLASSES] = {};
    const float* vrow = g_v + (size_t)n * HIDDEN;
    for (int h = tid; h < HIDDEN; h += 256) {
        float vv = vrow[h];
        const float* wrow = Wo + (size_t)h * CLASSES;
        #pragma unroll
        for (int c = 0; c < CLASSES; c++) acc[c] = fmaf(vv, wrow[c], acc[c]);
    }
    #pragma unroll
    for (int c = 0; c < CLASSES; c++)
        #pragma unroll
        for (int o = 16; o > 0; o >>= 1)
            acc[c] += __shfl_xor_sync(0xffffffffu, acc[c], o);
    __shared__ float part[8][CLASSES];
    if ((tid & 31) == 0) {
        #pragma unroll
        for (int c = 0; c < CLASSES; c++) part[tid >> 5][c] = acc[c];
    }
    __syncthreads();
    if (tid < CLASSES) {
        float s = 0.f;
        #pragma unroll
        for (int w = 0; w < 8; w++) s += part[w][tid];
        out[(size_t)n * CLASSES + tid] = s + bo[tid];
    }
}

// ==================== launch ====================
extern "C" void kernel_launch(void* const* d_in, const int* in_sizes, int n_in,
                              void* d_out, int out_size) {
    const float* x  = (const float*)d_in[0];
    const float* Wu = (const float*)d_in[1];
    const float* bu = (const float*)d_in[2];
    const float* Wv = (const float*)d_in[3];
    const float* bv = (const float*)d_in[4];
    const float* Wo = (const float*)d_in[5];
    const float* bo = (const float*)d_in[6];
    float* out = (float*)d_out;

    cudaFuncSetAttribute(k_gemm, cudaFuncAttributeMaxDynamicSharedMemorySize, SMEM_GEMM);

    k_transpose_x<<<(N_SAMPLES * D_FEAT + 255) / 256, 256>>>(x);
    k_prep<<<CONV_BLOCKS, 256>>>(Wv);
    k_gemm<<<dim3(HIDDEN / BN, N_SAMPLES / BM), 512, SMEM_GEMM>>>(Wu, bu, bv);
    k_final<<<N_SAMPLES, 256>>>(Wo, bo, out);
}

// round 12
// speedup vs baseline: 1.4569x; 1.4569x over previous
#include <cuda_runtime.h>
#include <cuda_fp16.h>
#include <cstdint>

// Problem dims
#define N_SAMPLES 2048
#define D_FEAT    64
#define P_PAIRS   2016
#define INNER     32
#define KDIM      64512   // P_PAIRS * INNER
#define HIDDEN    2048
#define CLASSES   10

// GEMM tiling
#define BM 128
#define BN 256
#define BK 64
#define STG 4
#define CHUNKS (KDIM / BK)                 // 1008
#define A_STAGE (BM * 128)                 // 16384 B
#define B_STAGE (BN * 128)                 // 32768 B
#define STAGE_B (A_STAGE + B_STAGE)        // 49152 B
#define OFF_MBAR (STG * STAGE_B)           // 196608
#define SMEM_GEMM (OFF_MBAR + 64)

// -------------------- scratch (device globals; no allocation) --------------------
__device__ __half g_u [(size_t)N_SAMPLES * KDIM];   // tiled [mb][c][row][kc^sw]
__device__ __half g_bt[(size_t)HIDDEN    * KDIM];   // tiled [nb][c][row][kc^sw]
__device__ float  g_v [(size_t)N_SAMPLES * HIDDEN];
__device__ float  g_xT[(size_t)D_FEAT * N_SAMPLES];

// -------------------- helpers --------------------
__device__ __forceinline__ uint32_t smem_u32(const void* p) {
    return (uint32_t)__cvta_generic_to_shared(p);
}
__device__ __forceinline__ void mbar_init(uint32_t addr, uint32_t count) {
    asm volatile("mbarrier.init.shared.b64 [%0], %1;" :: "r"(addr), "r"(count) : "memory");
}
__device__ __forceinline__ void mbar_expect_tx(uint32_t addr, uint32_t bytes) {
    asm volatile("mbarrier.arrive.expect_tx.shared.b64 _, [%0], %1;"
                 :: "r"(addr), "r"(bytes) : "memory");
}
__device__ __forceinline__ void mbar_arrive(uint32_t addr) {
    asm volatile("mbarrier.arrive.shared.b64 _, [%0];" :: "r"(addr) : "memory");
}
__device__ __forceinline__ void mbar_wait(uint32_t addr, uint32_t parity) {
    uint32_t done;
    asm volatile(
        "{\n\t.reg .pred p;\n\t"
        "mbarrier.try_wait.parity.acquire.cta.shared::cta.b64 p, [%1], %2;\n\t"
        "selp.b32 %0, 1, 0, p;\n\t}"
        : "=r"(done) : "r"(addr), "r"(parity) : "memory");
    if (!done) {
        asm volatile(
            "{\n\t.reg .pred P1;\n\t"
            "W_%=:\n\t"
            "mbarrier.try_wait.parity.acquire.cta.shared::cta.b64 P1, [%0], %1, 0x989680;\n\t"
            "@P1 bra.uni D_%=;\n\t"
            "bra.uni W_%=;\n\t"
            "D_%=:\n\t}"
            :: "r"(addr), "r"(parity) : "memory");
    }
}
__device__ __forceinline__ void bulk_g2s(uint32_t dstSmem, const void* srcGmem,
                                         uint32_t bytes, uint32_t mbar) {
    asm volatile(
        "cp.async.bulk.shared::cluster.global.mbarrier::complete_tx::bytes [%0], [%1], %2, [%3];"
        :: "r"(dstSmem), "l"(srcGmem), "r"(bytes), "r"(mbar) : "memory");
}
__device__ __forceinline__ void ldsm_x4(uint32_t* r, uint32_t addr) {
    asm volatile("ldmatrix.sync.aligned.m8n8.x4.shared.b16 {%0,%1,%2,%3}, [%4];"
                 : "=r"(r[0]), "=r"(r[1]), "=r"(r[2]), "=r"(r[3]) : "r"(addr));
}
__device__ __forceinline__ void mma16816(float* c, const uint32_t* a, const uint32_t* b) {
    asm volatile(
        "mma.sync.aligned.m16n8k16.row.col.f32.f16.f16.f32 "
        "{%0,%1,%2,%3}, {%4,%5,%6,%7}, {%8,%9}, {%0,%1,%2,%3};"
        : "+f"(c[0]), "+f"(c[1]), "+f"(c[2]), "+f"(c[3])
        : "r"(a[0]), "r"(a[1]), "r"(a[2]), "r"(a[3]), "r"(b[0]), "r"(b[1]));
}
__device__ __forceinline__ uint32_t sw_off(int row, int kc) {
    return (uint32_t)(row * 128 + ((kc ^ (row & 7)) << 4));
}

// ==================== kernel 1: transpose x ====================
__global__ void k_transpose_x(const float* __restrict__ x) {
    int idx = blockIdx.x * blockDim.x + threadIdx.x;
    if (idx < N_SAMPLES * D_FEAT) {
        int n = idx >> 6, d = idx & 63;
        g_xT[(size_t)d * N_SAMPLES + n] = x[idx];
    }
}

// ==================== kernel 2 (fused): pairwise MLP + Wv transpose/convert ====================
// blocks [0, P_PAIRS): pairwise Linear(2,32)+ReLU -> g_u (R6-identical)
// blocks [P_PAIRS, +32256): Wv conv, 64k x 64n tiles, float4 loads, 1 barrier
#define CONV_BLOCKS (CHUNKS * (HIDDEN / 64))   // 1008 * 32 = 32256

__global__ void k_prep(const float* __restrict__ Wu, const float* __restrict__ bu,
                       const float* __restrict__ Wv) {
    int tid = threadIdx.x;
    if (blockIdx.x < P_PAIRS) {
        int p = blockIdx.x;
        int a = 0, rem = p;
        while (rem >= (D_FEAT - 1 - a)) { rem -= (D_FEAT - 1 - a); a++; }
        int b = a + 1 + rem;

        __shared__ float w0[INNER], w1[INNER], bb[INNER];
        if (tid < INNER) {
            w0[tid] = Wu[(size_t)p * 2 * INNER + tid];
            w1[tid] = Wu[(size_t)p * 2 * INNER + INNER + tid];
            bb[tid] = bu[(size_t)p * INNER + tid];
        }
        __syncthreads();

        int c = p >> 1;        // k-chunk
        int h = p & 1;         // which half of the 128B row
        uint4* g_u_u4 = reinterpret_cast<uint4*>(g_u);
        const float* xa = g_xT + (size_t)a * N_SAMPLES;
        const float* xb = g_xT + (size_t)b * N_SAMPLES;
        for (int n = tid; n < N_SAMPLES; n += blockDim.x) {
            float va = xa[n], vb = xb[n];
            __half2 outv[INNER / 2];
            #pragma unroll
            for (int i = 0; i < INNER; i += 2) {
                float r0 = fmaf(va, w0[i],     fmaf(vb, w1[i],     bb[i]));
                float r1 = fmaf(va, w0[i + 1], fmaf(vb, w1[i + 1], bb[i + 1]));
                outv[i / 2] = __floats2half2_rn(fmaxf(r0, 0.f), fmaxf(r1, 0.f));
            }
            const uint4* src = reinterpret_cast<const uint4*>(outv);
            int mb = n >> 7, row = n & 127;
            size_t base8 = ((size_t)(mb * CHUNKS + c) * 128 + row) * 8;
            #pragma unroll
            for (int q = 0; q < 4; q++) {
                int kc = h * 4 + q;
                g_u_u4[base8 + (kc ^ (row & 7))] = src[q];
            }
        }
    } else {
        // ---- conv: chunk c (64 k-rows) x 64 n, float4 loads, single barrier ----
        int bid = blockIdx.x - P_PAIRS;
        int c = bid >> 5;                  // 1008 chunks
        int nt0 = (bid & 31) * 64;         // 32 n-tiles of 64
        __shared__ float tile[64][65];
        #pragma unroll
        for (int p4 = 0; p4 < 4; p4++) {   // 64 rows x 16 float4 = 1024 f4, 4/thread
            int idx = tid + p4 * 256;
            int kl = idx >> 4, c4 = idx & 15;
            float4 v = *reinterpret_cast<const float4*>(
                Wv + (size_t)(c * 64 + kl) * HIDDEN + nt0 + c4 * 4);
            tile[kl][c4 * 4 + 0] = v.x;
            tile[kl][c4 * 4 + 1] = v.y;
            tile[kl][c4 * 4 + 2] = v.z;
            tile[kl][c4 * 4 + 3] = v.w;
        }
        __syncthreads();
        // write: thread -> n_local = tid>>2, uq = tid&3; emits units uq and uq+4
        int nl = tid >> 2, uq = tid & 3;
        int n = nt0 + nl;
        int nb = n >> 8, rowB = n & 255;
        size_t base8 = ((size_t)(nb * CHUNKS + c) * 256 + rowB) * 8;
        #pragma unroll
        for (int h = 0; h < 2; h++) {
            int kc = uq + h * 4;
            __half hp[8];
            #pragma unroll
            for (int j = 0; j < 8; j++) hp[j] = __float2half(tile[kc * 8 + j][nl]);
            reinterpret_cast<uint4*>(g_bt)[base8 + (kc ^ (rowB & 7))] =
                *reinterpret_cast<uint4*>(hp);
        }
    }
}

// ==================== kernel 3: big GEMM v = relu(u @ Wv + bv) — R6 exact ====================
__global__ void __launch_bounds__(512, 1) k_gemm(const float* __restrict__ bv) {
    extern __shared__ char smem[];
    uint32_t sbase = smem_u32(smem);
    int tid = threadIdx.x;
    int lane = tid & 31;
    int wid = tid >> 5;          // 0..15
    int wm = wid >> 3;           // 0..1  (64 rows each)
    int wn = wid & 7;            // 0..7  (32 cols each)
    int nb = blockIdx.x;         // 8 n-blocks
    int mb = blockIdx.y;         // 16 m-blocks

    const char* gA = (const char*)g_u  + (size_t)mb * CHUNKS * A_STAGE;
    const char* gB = (const char*)g_bt + (size_t)nb * CHUNKS * B_STAGE;

    uint32_t mfull = sbase + OFF_MBAR;
    uint32_t mempty = sbase + OFF_MBAR + 32;
    if (tid == 0) {
        #pragma unroll
        for (int s = 0; s < STG; s++) {
            mbar_init(mfull + s * 8, 1);
            mbar_init(mempty + s * 8, 16);
        }
    }
    __syncthreads();

    // prologue: fill stages 0..STG-2
    if (tid == 0) {
        #pragma unroll
        for (int s = 0; s < STG - 1; s++) {
            mbar_expect_tx(mfull + s * 8, STAGE_B);
            bulk_g2s(sbase + s * STAGE_B,           gA + (size_t)s * A_STAGE, A_STAGE, mfull + s * 8);
            bulk_g2s(sbase + s * STAGE_B + A_STAGE, gB + (size_t)s * B_STAGE, B_STAGE, mfull + s * 8);
        }
    }

    int g = lane >> 3, sub = lane & 7;
    int rowA_base = wm * 64 + ((g & 1) << 3) + sub;
    int kcA_base  = g >> 1;
    int rowB_base = wn * 32 + ((g >> 1) << 3) + sub;
    int kcB_base  = g & 1;

    float acc[4][4][4];
    #pragma unroll
    for (int i = 0; i < 4; i++)
        #pragma unroll
        for (int j = 0; j < 4; j++)
            #pragma unroll
            for (int t = 0; t < 4; t++) acc[i][j][t] = 0.f;

    for (int k = 0; k < CHUNKS; k++) {
        int slot = k & 3;
        if (wid == 0) {
            int kp = k + STG - 1;
            if (kp < CHUNKS) {
                int sp = kp & 3;
                if (kp >= STG) mbar_wait(mempty + sp * 8, ((kp >> 2) + 1) & 1);
                if (lane == 0) {
                    mbar_expect_tx(mfull + sp * 8, STAGE_B);
                    bulk_g2s(sbase + sp * STAGE_B,           gA + (size_t)kp * A_STAGE, A_STAGE, mfull + sp * 8);
                    bulk_g2s(sbase + sp * STAGE_B + A_STAGE, gB + (size_t)kp * B_STAGE, B_STAGE, mfull + sp * 8);
                }
            }
        }

        mbar_wait(mfull + slot * 8, (k >> 2) & 1);

        uint32_t aS = sbase + slot * STAGE_B;
        uint32_t bS = aS + A_STAGE;
        #pragma unroll
        for (int ks = 0; ks < 4; ks++) {
            uint32_t afr[4][4], bfr[2][4];
            #pragma unroll
            for (int q = 0; q < 2; q++) {
                int row = rowB_base + q * 16;
                ldsm_x4(bfr[q], bS + sw_off(row, ks * 2 + kcB_base));
            }
            #pragma unroll
            for (int mt = 0; mt < 4; mt++) {
                int row = rowA_base + mt * 16;
                ldsm_x4(afr[mt], aS + sw_off(row, ks * 2 + kcA_base));
            }
            #pragma unroll
            for (int mt = 0; mt < 4; mt++)
                #pragma unroll
                for (int nt = 0; nt < 4; nt++)
                    mma16816(acc[mt][nt], afr[mt], &bfr[nt >> 1][(nt & 1) * 2]);
        }
        if (lane == 0) mbar_arrive(mempty + slot * 8);
    }

    // epilogue: bias + relu, write fp32 v
    int rlo = lane >> 2;
    int cpair = (lane & 3) * 2;
    int bn0 = nb * BN, bm0 = mb * BM;
    #pragma unroll
    for (int mt = 0; mt < 4; mt++) {
        #pragma unroll
        for (int nt = 0; nt < 4; nt++) {
            int col = bn0 + wn * 32 + nt * 8 + cpair;
            float b0 = __ldg(bv + col), b1 = __ldg(bv + col + 1);
            int row0 = bm0 + wm * 64 + mt * 16 + rlo;
            float2 o0, o1;
            o0.x = fmaxf(acc[mt][nt][0] + b0, 0.f);
            o0.y = fmaxf(acc[mt][nt][1] + b1, 0.f);
            o1.x = fmaxf(acc[mt][nt][2] + b0, 0.f);
            o1.y = fmaxf(acc[mt][nt][3] + b1, 0.f);
            *reinterpret_cast<float2*>(g_v + (size_t)row0 * HIDDEN + col) = o0;
            *reinterpret_cast<float2*>(g_v + (size_t)(row0 + 8) * HIDDEN + col) = o1;
        }
    }
}

// ==================== kernel 4: head  out = v @ Wo + bo ====================
__global__ void k_final(const float* __restrict__ Wo, const float* __restrict__ bo,
                        float* __restrict__ out) {
    int n = blockIdx.x, tid = threadIdx.x;
    float acc[CLASSES] = {};
    const float* vrow = g_v + (size_t)n * HIDDEN;
    for (int h = tid; h < HIDDEN; h += 256) {
        float vv = vrow[h];
        const float* wrow = Wo + (size_t)h * CLASSES;
        #pragma unroll
        for (int c = 0; c < CLASSES; c++) acc[c] = fmaf(vv, wrow[c], acc[c]);
    }
    #pragma unroll
    for (int c = 0; c < CLASSES; c++)
        #pragma unroll
        for (int o = 16; o > 0; o >>= 1)
            acc[c] += __shfl_xor_sync(0xffffffffu, acc[c], o);
    __shared__ float part[8][CLASSES];
    if ((tid & 31) == 0) {
        #pragma unroll
        for (int c = 0; c < CLASSES; c++) part[tid >> 5][c] = acc[c];
    }
    __syncthreads();
    if (tid < CLASSES) {
        float s = 0.f;
        #pragma unroll
        for (int w = 0; w < 8; w++) s += part[w][tid];
        out[(size_t)n * CLASSES + tid] = s + bo[tid];
    }
}

// ==================== launch ====================
extern "C" void kernel_launch(void* const* d_in, const int* in_sizes, int n_in,
                              void* d_out, int out_size) {
    const float* x  = (const float*)d_in[0];
    const float* Wu = (const float*)d_in[1];
    const float* bu = (const float*)d_in[2];
    const float* Wv = (const float*)d_in[3];
    const float* bv = (const float*)d_in[4];
    const float* Wo = (const float*)d_in[5];
    const float* bo = (const float*)d_in[6];
    float* out = (float*)d_out;

    cudaFuncSetAttribute(k_gemm, cudaFuncAttributeMaxDynamicSharedMemorySize, SMEM_GEMM);

    k_transpose_x<<<(N_SAMPLES * D_FEAT + 255) / 256, 256>>>(x);
    k_prep<<<P_PAIRS + CONV_BLOCKS, 256>>>(Wu, bu, Wv);
    k_gemm<<<dim3(HIDDEN / BN, N_SAMPLES / BM), 512, SMEM_GEMM>>>(bv);
    k_final<<<N_SAMPLES, 256>>>(Wo, bo, out);
}

// round 13
// speedup vs baseline: 1.5577x; 1.0692x over previous
#include <cuda_runtime.h>
#include <cuda_fp16.h>
#include <cstdint>

// Problem dims
#define N_SAMPLES 2048
#define D_FEAT    64
#define P_PAIRS   2016
#define INNER     32
#define KDIM      64512   // P_PAIRS * INNER
#define HIDDEN    2048
#define CLASSES   10

// GEMM tiling
#define BM 128
#define BN 256
#define BK 64
#define STG 4
#define CHUNKS (KDIM / BK)                 // 1008
#define A_STAGE (BM * 128)                 // 16384 B
#define B_STAGE (BN * 128)                 // 32768 B
#define STAGE_B (A_STAGE + B_STAGE)        // 49152 B
#define OFF_MBAR (STG * STAGE_B)           // 196608
#define SMEM_GEMM (OFF_MBAR + 64)

// -------------------- scratch (device globals; no allocation) --------------------
__device__ __half g_u [(size_t)N_SAMPLES * KDIM];   // tiled [mb][c][row][kc^sw]
__device__ __half g_bt[(size_t)HIDDEN    * KDIM];   // tiled [nb][c][row][kc^sw]
__device__ float  g_v [(size_t)N_SAMPLES * HIDDEN];
__device__ float  g_xT[(size_t)D_FEAT * N_SAMPLES];

// -------------------- helpers --------------------
__device__ __forceinline__ uint32_t smem_u32(const void* p) {
    return (uint32_t)__cvta_generic_to_shared(p);
}
__device__ __forceinline__ void mbar_init(uint32_t addr, uint32_t count) {
    asm volatile("mbarrier.init.shared.b64 [%0], %1;" :: "r"(addr), "r"(count) : "memory");
}
__device__ __forceinline__ void mbar_expect_tx(uint32_t addr, uint32_t bytes) {
    asm volatile("mbarrier.arrive.expect_tx.shared.b64 _, [%0], %1;"
                 :: "r"(addr), "r"(bytes) : "memory");
}
__device__ __forceinline__ void mbar_arrive(uint32_t addr) {
    asm volatile("mbarrier.arrive.shared.b64 _, [%0];" :: "r"(addr) : "memory");
}
__device__ __forceinline__ void mbar_wait(uint32_t addr, uint32_t parity) {
    uint32_t done;
    asm volatile(
        "{\n\t.reg .pred p;\n\t"
        "mbarrier.try_wait.parity.acquire.cta.shared::cta.b64 p, [%1], %2;\n\t"
        "selp.b32 %0, 1, 0, p;\n\t}"
        : "=r"(done) : "r"(addr), "r"(parity) : "memory");
    if (!done) {
        asm volatile(
            "{\n\t.reg .pred P1;\n\t"
            "W_%=:\n\t"
            "mbarrier.try_wait.parity.acquire.cta.shared::cta.b64 P1, [%0], %1, 0x989680;\n\t"
            "@P1 bra.uni D_%=;\n\t"
            "bra.uni W_%=;\n\t"
            "D_%=:\n\t}"
            :: "r"(addr), "r"(parity) : "memory");
    }
}
__device__ __forceinline__ void bulk_g2s(uint32_t dstSmem, const void* srcGmem,
                                         uint32_t bytes, uint32_t mbar) {
    asm volatile(
        "cp.async.bulk.shared::cluster.global.mbarrier::complete_tx::bytes [%0], [%1], %2, [%3];"
        :: "r"(dstSmem), "l"(srcGmem), "r"(bytes), "r"(mbar) : "memory");
}
__device__ __forceinline__ void ldsm_x4(uint32_t* r, uint32_t addr) {
    asm volatile("ldmatrix.sync.aligned.m8n8.x4.shared.b16 {%0,%1,%2,%3}, [%4];"
                 : "=r"(r[0]), "=r"(r[1]), "=r"(r[2]), "=r"(r[3]) : "r"(addr));
}
__device__ __forceinline__ void mma16816(float* c, const uint32_t* a, const uint32_t* b) {
    asm volatile(
        "mma.sync.aligned.m16n8k16.row.col.f32.f16.f16.f32 "
        "{%0,%1,%2,%3}, {%4,%5,%6,%7}, {%8,%9}, {%0,%1,%2,%3};"
        : "+f"(c[0]), "+f"(c[1]), "+f"(c[2]), "+f"(c[3])
        : "r"(a[0]), "r"(a[1]), "r"(a[2]), "r"(a[3]), "r"(b[0]), "r"(b[1]));
}
__device__ __forceinline__ uint32_t sw_off(int row, int kc) {
    return (uint32_t)(row * 128 + ((kc ^ (row & 7)) << 4));
}

// ==================== kernel 1: transpose x ====================
__global__ void k_transpose_x(const float* __restrict__ x) {
    int idx = blockIdx.x * blockDim.x + threadIdx.x;
    if (idx < N_SAMPLES * D_FEAT) {
        int n = idx >> 6, d = idx & 63;
        g_xT[(size_t)d * N_SAMPLES + n] = x[idx];
    }
}

// ==================== kernel 2 (fused): pairwise MLP + Wv transpose/convert ====================
// blocks [0, CHUNKS): pairwise MLP for chunk c (pairs 2c, 2c+1), fully coalesced writes
// blocks [CHUNKS, +32256): Wv conv (R12 version, float4 loads)
#define CONV_BLOCKS (CHUNKS * (HIDDEN / 64))   // 32256

__global__ void k_prep(const float* __restrict__ Wu, const float* __restrict__ bu,
                       const float* __restrict__ Wv) {
    int tid = threadIdx.x;
    if (blockIdx.x < CHUNKS) {
        // ---- pairs: chunk c = pairs 2c, 2c+1; lane kc = tid&7 owns one 16B unit per row ----
        int c = blockIdx.x;
        int kc = tid & 7;           // 16B unit within 128B row
        int pp = kc >> 2;           // 0 -> pair 2c, 1 -> pair 2c+1
        int p = c * 2 + pp;
        int i0 = (kc & 3) * 8;      // inner offset within pair's 32 outputs
        // pair index -> (a, b)
        int a = 0, rem = p;
        while (rem >= (D_FEAT - 1 - a)) { rem -= (D_FEAT - 1 - a); a++; }
        int b = a + 1 + rem;
        // loop-invariant weight slice in registers
        float w0v[8], w1v[8], bbv[8];
        #pragma unroll
        for (int j = 0; j < 8; j++) {
            w0v[j] = __ldg(Wu + (size_t)p * 64 + i0 + j);
            w1v[j] = __ldg(Wu + (size_t)p * 64 + 32 + i0 + j);
            bbv[j] = __ldg(bu + (size_t)p * 32 + i0 + j);
        }
        const float* xa = g_xT + (size_t)a * N_SAMPLES;
        const float* xb = g_xT + (size_t)b * N_SAMPLES;
        uint4* g_u_u4 = reinterpret_cast<uint4*>(g_u);
        int rbase = tid >> 3;       // 0..31
        #pragma unroll 1
        for (int pass = 0; pass < 64; pass++) {
            int n = pass * 32 + rbase;
            float va = __ldg(xa + n), vb = __ldg(xb + n);
            __half2 ov[4];
            #pragma unroll
            for (int j = 0; j < 8; j += 2) {
                float r0 = fmaf(va, w0v[j],     fmaf(vb, w1v[j],     bbv[j]));
                float r1 = fmaf(va, w0v[j + 1], fmaf(vb, w1v[j + 1], bbv[j + 1]));
                ov[j >> 1] = __floats2half2_rn(fmaxf(r0, 0.f), fmaxf(r1, 0.f));
            }
            int mb = n >> 7, row = n & 127;
            size_t unit = ((size_t)(mb * CHUNKS + c) * 128 + row) * 8 + (kc ^ (row & 7));
            g_u_u4[unit] = *reinterpret_cast<uint4*>(ov);
        }
    } else {
        // ---- conv: chunk c (64 k-rows) x 64 n, float4 loads, single barrier (R12) ----
        int bid = blockIdx.x - CHUNKS;
        int c = bid >> 5;
        int nt0 = (bid & 31) * 64;
        __shared__ float tile[64][65];
        #pragma unroll
        for (int p4 = 0; p4 < 4; p4++) {
            int idx = tid + p4 * 256;
            int kl = idx >> 4, c4 = idx & 15;
            float4 v = *reinterpret_cast<const float4*>(
                Wv + (size_t)(c * 64 + kl) * HIDDEN + nt0 + c4 * 4);
            tile[kl][c4 * 4 + 0] = v.x;
            tile[kl][c4 * 4 + 1] = v.y;
            tile[kl][c4 * 4 + 2] = v.z;
            tile[kl][c4 * 4 + 3] = v.w;
        }
        __syncthreads();
        int nl = tid >> 2, uq = tid & 3;
        int n = nt0 + nl;
        int nb = n >> 8, rowB = n & 255;
        size_t base8 = ((size_t)(nb * CHUNKS + c) * 256 + rowB) * 8;
        #pragma unroll
        for (int h = 0; h < 2; h++) {
            int kc = uq + h * 4;
            __half hp[8];
            #pragma unroll
            for (int j = 0; j < 8; j++) hp[j] = __float2half(tile[kc * 8 + j][nl]);
            reinterpret_cast<uint4*>(g_bt)[base8 + (kc ^ (rowB & 7))] =
                *reinterpret_cast<uint4*>(hp);
        }
    }
}

// ==================== kernel 3: big GEMM v = relu(u @ Wv + bv) — R6/R12 exact ====================
__global__ void __launch_bounds__(512, 1) k_gemm(const float* __restrict__ bv) {
    extern __shared__ char smem[];
    uint32_t sbase = smem_u32(smem);
    int tid = threadIdx.x;
    int lane = tid & 31;
    int wid = tid >> 5;          // 0..15
    int wm = wid >> 3;           // 0..1  (64 rows each)
    int wn = wid & 7;            // 0..7  (32 cols each)
    int nb = blockIdx.x;         // 8 n-blocks
    int mb = blockIdx.y;         // 16 m-blocks

    const char* gA = (const char*)g_u  + (size_t)mb * CHUNKS * A_STAGE;
    const char* gB = (const char*)g_bt + (size_t)nb * CHUNKS * B_STAGE;

    uint32_t mfull = sbase + OFF_MBAR;
    uint32_t mempty = sbase + OFF_MBAR + 32;
    if (tid == 0) {
        #pragma unroll
        for (int s = 0; s < STG; s++) {
            mbar_init(mfull + s * 8, 1);
            mbar_init(mempty + s * 8, 16);
        }
    }
    __syncthreads();

    if (tid == 0) {
        #pragma unroll
        for (int s = 0; s < STG - 1; s++) {
            mbar_expect_tx(mfull + s * 8, STAGE_B);
            bulk_g2s(sbase + s * STAGE_B,           gA + (size_t)s * A_STAGE, A_STAGE, mfull + s * 8);
            bulk_g2s(sbase + s * STAGE_B + A_STAGE, gB + (size_t)s * B_STAGE, B_STAGE, mfull + s * 8);
        }
    }

    int g = lane >> 3, sub = lane & 7;
    int rowA_base = wm * 64 + ((g & 1) << 3) + sub;
    int kcA_base  = g >> 1;
    int rowB_base = wn * 32 + ((g >> 1) << 3) + sub;
    int kcB_base  = g & 1;

    float acc[4][4][4];
    #pragma unroll
    for (int i = 0; i < 4; i++)
        #pragma unroll
        for (int j = 0; j < 4; j++)
            #pragma unroll
            for (int t = 0; t < 4; t++) acc[i][j][t] = 0.f;

    for (int k = 0; k < CHUNKS; k++) {
        int slot = k & 3;
        if (wid == 0) {
            int kp = k + STG - 1;
            if (kp < CHUNKS) {
                int sp = kp & 3;
                if (kp >= STG) mbar_wait(mempty + sp * 8, ((kp >> 2) + 1) & 1);
                if (lane == 0) {
                    mbar_expect_tx(mfull + sp * 8, STAGE_B);
                    bulk_g2s(sbase + sp * STAGE_B,           gA + (size_t)kp * A_STAGE, A_STAGE, mfull + sp * 8);
                    bulk_g2s(sbase + sp * STAGE_B + A_STAGE, gB + (size_t)kp * B_STAGE, B_STAGE, mfull + sp * 8);
                }
            }
        }

        mbar_wait(mfull + slot * 8, (k >> 2) & 1);

        uint32_t aS = sbase + slot * STAGE_B;
        uint32_t bS = aS + A_STAGE;
        #pragma unroll
        for (int ks = 0; ks < 4; ks++) {
            uint32_t afr[4][4], bfr[2][4];
            #pragma unroll
            for (int q = 0; q < 2; q++) {
                int row = rowB_base + q * 16;
                ldsm_x4(bfr[q], bS + sw_off(row, ks * 2 + kcB_base));
            }
            #pragma unroll
            for (int mt = 0; mt < 4; mt++) {
                int row = rowA_base + mt * 16;
                ldsm_x4(afr[mt], aS + sw_off(row, ks * 2 + kcA_base));
            }
            #pragma unroll
            for (int mt = 0; mt < 4; mt++)
                #pragma unroll
                for (int nt = 0; nt < 4; nt++)
                    mma16816(acc[mt][nt], afr[mt], &bfr[nt >> 1][(nt & 1) * 2]);
        }
        if (lane == 0) mbar_arrive(mempty + slot * 8);
    }

    // epilogue: bias + relu, write fp32 v
    int rlo = lane >> 2;
    int cpair = (lane & 3) * 2;
    int bn0 = nb * BN, bm0 = mb * BM;
    #pragma unroll
    for (int mt = 0; mt < 4; mt++) {
        #pragma unroll
        for (int nt = 0; nt < 4; nt++) {
            int col = bn0 + wn * 32 + nt * 8 + cpair;
            float b0 = __ldg(bv + col), b1 = __ldg(bv + col + 1);
            int row0 = bm0 + wm * 64 + mt * 16 + rlo;
            float2 o0, o1;
            o0.x = fmaxf(acc[mt][nt][0] + b0, 0.f);
            o0.y = fmaxf(acc[mt][nt][1] + b1, 0.f);
            o1.x = fmaxf(acc[mt][nt][2] + b0, 0.f);
            o1.y = fmaxf(acc[mt][nt][3] + b1, 0.f);
            *reinterpret_cast<float2*>(g_v + (size_t)row0 * HIDDEN + col) = o0;
            *reinterpret_cast<float2*>(g_v + (size_t)(row0 + 8) * HIDDEN + col) = o1;
        }
    }
}

// ==================== kernel 4: head — 8 samples per block, Wo reused across samples ====================
__global__ void __launch_bounds__(256) k_final(const float* __restrict__ Wo,
                                               const float* __restrict__ bo,
                                               float* __restrict__ out) {
    int n0 = blockIdx.x * 8;     // 256 blocks
    int tid = threadIdx.x;
    int lane = tid & 31, wid = tid >> 5;

    float acc[8][CLASSES];
    #pragma unroll
    for (int s = 0; s < 8; s++)
        #pragma unroll
        for (int c = 0; c < CLASSES; c++) acc[s][c] = 0.f;

    for (int h = tid; h < HIDDEN; h += 256) {
        float w[CLASSES];
        const float2* wrow = reinterpret_cast<const float2*>(Wo + (size_t)h * CLASSES);
        #pragma unroll
        for (int c2 = 0; c2 < CLASSES / 2; c2++) {
            float2 ww = __ldg(wrow + c2);
            w[c2 * 2] = ww.x; w[c2 * 2 + 1] = ww.y;
        }
        #pragma unroll
        for (int s = 0; s < 8; s++) {
            float vv = g_v[(size_t)(n0 + s) * HIDDEN + h];
            #pragma unroll
            for (int c = 0; c < CLASSES; c++) acc[s][c] = fmaf(vv, w[c], acc[s][c]);
        }
    }
    // warp reduce
    #pragma unroll
    for (int s = 0; s < 8; s++)
        #pragma unroll
        for (int c = 0; c < CLASSES; c++)
            #pragma unroll
            for (int o = 16; o > 0; o >>= 1)
                acc[s][c] += __shfl_xor_sync(0xffffffffu, acc[s][c], o);

    __shared__ float part[8][8][CLASSES];
    if (lane == 0) {
        #pragma unroll
        for (int s = 0; s < 8; s++)
            #pragma unroll
            for (int c = 0; c < CLASSES; c++) part[wid][s][c] = acc[s][c];
    }
    __syncthreads();
    if (tid < 8 * CLASSES) {
        int s = tid / CLASSES, c = tid % CLASSES;
        float sum = 0.f;
        #pragma unroll
        for (int w = 0; w < 8; w++) sum += part[w][s][c];
        out[(size_t)(n0 + s) * CLASSES + c] = sum + bo[c];
    }
}

// ==================== launch ====================
extern "C" void kernel_launch(void* const* d_in, const int* in_sizes, int n_in,
                              void* d_out, int out_size) {
    const float* x  = (const float*)d_in[0];
    const float* Wu = (const float*)d_in[1];
    const float* bu = (const float*)d_in[2];
    const float* Wv = (const float*)d_in[3];
    const float* bv = (const float*)d_in[4];
    const float* Wo = (const float*)d_in[5];
    const float* bo = (const float*)d_in[6];
    float* out = (float*)d_out;

    cudaFuncSetAttribute(k_gemm, cudaFuncAttributeMaxDynamicSharedMemorySize, SMEM_GEMM);

    k_transpose_x<<<(N_SAMPLES * D_FEAT + 255) / 256, 256>>>(x);
    k_prep<<<CHUNKS + CONV_BLOCKS, 256>>>(Wu, bu, Wv);
    k_gemm<<<dim3(HIDDEN / BN, N_SAMPLES / BM), 512, SMEM_GEMM>>>(bv);
    k_final<<<N_SAMPLES / 8, 256>>>(Wo, bo, out);
}